// round 4
// baseline (speedup 1.0000x reference)
#include <cuda_runtime.h>
#include <cstdint>

#define N_NODES   50000
#define N_EDGES   800000
#define DIM       128
#define MASK_N    6400000   // N_NODES*DIM

// ---------------- scratch (static device globals; no allocations) ----------
__device__ float g_deg[N_NODES];
__device__ float g_dinv[N_NODES];
__device__ int   g_cnt[N_NODES];
__device__ int   g_off[N_NODES + 1];
__device__ int   g_cur[N_NODES];
__device__ int   g_src[N_EDGES];
__device__ float g_nrm[N_EDGES];
__device__ float g_t[N_NODES * DIM];   // GEMM output (per layer)
__device__ float g_h[N_NODES * DIM];   // layer-1 activation
__device__ unsigned char g_keep[N_NODES * DIM];
__device__ int   g_is64;               // edge_index buffer dtype flag

// ---------------- dtype detect: int64 => all odd int32 words are zero -------
__global__ void k_detect(const int* __restrict__ ei32, int n32) {
    __shared__ int sh_any;
    if (threadIdx.x == 0) sh_any = 0;
    __syncthreads();
    int nz = 0;
    for (int i = threadIdx.x; i < 4096; i += blockDim.x) {
        int p = 2 * i + 1;
        if (p < n32 && ei32[p] != 0) nz = 1;
    }
    if (nz) atomicOr(&sh_any, 1);
    __syncthreads();
    if (threadIdx.x == 0) g_is64 = sh_any ? 0 : 1;
}

// ---------------- init ------------------------------------------------------
__global__ void k_init() {
    int i = blockIdx.x * blockDim.x + threadIdx.x;
    if (i < N_NODES) { g_deg[i] = 2.0f; g_cnt[i] = 0; }  // self-loop weight 2
}

__device__ __forceinline__ int load_idx(const void* ei, int pos) {
    if (g_is64) return (int)((const long long*)ei)[pos];
    return ((const int*)ei)[pos];
}

// ---------------- degree + per-col counts -----------------------------------
__global__ void k_deg(const void* __restrict__ ei,
                      const float* __restrict__ ew, int E) {
    int e = blockIdx.x * blockDim.x + threadIdx.x;
    if (e >= E) return;
    int c = load_idx(ei, E + e);
    if ((unsigned)c < N_NODES) {
        atomicAdd(&g_deg[c], ew[e]);
        atomicAdd(&g_cnt[c], 1);
    }
}

__global__ void k_dinv() {
    int i = blockIdx.x * blockDim.x + threadIdx.x;
    if (i < N_NODES) {
        float d = g_deg[i];
        g_dinv[i] = (d > 0.0f) ? rsqrtf(d) : 0.0f;
    }
}

// ---------------- single-block exclusive scan of g_cnt -> g_off, g_cur ------
__global__ void k_scan() {
    __shared__ int sh_warp[32];
    __shared__ int sh_carry;
    int tid = threadIdx.x, lane = tid & 31, wid = tid >> 5;
    if (tid == 0) sh_carry = 0;
    __syncthreads();
    for (int base = 0; base < N_NODES; base += 1024) {
        int i = base + tid;
        int v = (i < N_NODES) ? g_cnt[i] : 0;
        int x = v;
        #pragma unroll
        for (int o = 1; o < 32; o <<= 1) {
            int y = __shfl_up_sync(0xFFFFFFFFu, x, o);
            if (lane >= o) x += y;
        }
        if (lane == 31) sh_warp[wid] = x;
        __syncthreads();
        if (wid == 0) {
            int s = sh_warp[lane];
            #pragma unroll
            for (int o = 1; o < 32; o <<= 1) {
                int y = __shfl_up_sync(0xFFFFFFFFu, s, o);
                if (lane >= o) s += y;
            }
            sh_warp[lane] = s;
        }
        __syncthreads();
        int warppref = (wid == 0) ? 0 : sh_warp[wid - 1];
        int incl = x + warppref;
        int excl = sh_carry + incl - v;
        if (i < N_NODES) { g_off[i] = excl; g_cur[i] = excl; }
        __syncthreads();
        if (tid == 1023) sh_carry += sh_warp[31];
        __syncthreads();
    }
    if (threadIdx.x == 0) g_off[N_NODES] = sh_carry;
}

// ---------------- CSR fill + edge norms -------------------------------------
__global__ void k_fill(const void* __restrict__ ei,
                       const float* __restrict__ ew, int E) {
    int e = blockIdx.x * blockDim.x + threadIdx.x;
    if (e >= E) return;
    int r = load_idx(ei, e);
    int c = load_idx(ei, E + e);
    if ((unsigned)r >= N_NODES || (unsigned)c >= N_NODES) return;
    int p = atomicAdd(&g_cur[c], 1);
    if ((unsigned)p < N_EDGES) {
        g_src[p] = r;
        g_nrm[p] = g_dinv[r] * ew[e] * g_dinv[c];
    }
}

// ---------------- JAX threefry2x32 dropout mask ------------------------------
// Modern JAX: jax_threefry_partitionable=True, x64 off (device buffers are
// int32, proven round 1). random bits for element i (32-bit width):
//   counter = uint64 iota => (c0, c1) = (i >> 32, i & 0xffffffff) = (0, i)
//   (x0, x1) = threefry2x32(key=(0,42), (c0, c1))
//   bits     = x0 ^ x1                      (32-bit fold, partitionable path)
//   u        = bitcast((bits>>9)|0x3f800000) - 1;  keep = u < 0.5 <=> bit31==0
__device__ __forceinline__ unsigned rotl32(unsigned v, int d) {
    return (v << d) | (v >> (32 - d));
}
__device__ __forceinline__ void threefry2x32(unsigned c0, unsigned c1,
                                             unsigned& o0, unsigned& o1) {
    const unsigned k0 = 0u, k1 = 42u;
    const unsigned k2 = k0 ^ k1 ^ 0x1BD11BDAu;
    unsigned x0 = c0 + k0, x1 = c1 + k1;
#define TF_R(rot) { x0 += x1; x1 = rotl32(x1, rot); x1 ^= x0; }
    TF_R(13) TF_R(15) TF_R(26) TF_R(6)   x0 += k1; x1 += k2 + 1u;
    TF_R(17) TF_R(29) TF_R(16) TF_R(24)  x0 += k2; x1 += k0 + 2u;
    TF_R(13) TF_R(15) TF_R(26) TF_R(6)   x0 += k0; x1 += k1 + 3u;
    TF_R(17) TF_R(29) TF_R(16) TF_R(24)  x0 += k1; x1 += k2 + 4u;
    TF_R(13) TF_R(15) TF_R(26) TF_R(6)   x0 += k2; x1 += k0 + 5u;
#undef TF_R
    o0 = x0; o1 = x1;
}

__global__ void k_mask() {
    int e = blockIdx.x * blockDim.x + threadIdx.x;
    if (e >= MASK_N) return;
    unsigned x0, x1;
    threefry2x32(0u, (unsigned)e, x0, x1);
    unsigned bits = x0 ^ x1;
    g_keep[e] = (unsigned char)(1u ^ (bits >> 31));
}

// ---------------- GEMM: T = X @ W  (X: [N,128], W: [128,128]) ---------------
__global__ void k_gemm(const float* __restrict__ Xext,
                       const float* __restrict__ W, int useH) {
    __shared__ float xs[64][64];     // 16KB: M x Kchunk
    __shared__ float ws[64][128];    // 32KB: Kchunk x N
    const float* X = useH ? g_h : Xext;

    int tid = threadIdx.x;
    int blockRow = blockIdx.x * 64;
    int warp = tid >> 5, lane = tid & 31;
    int rbase = warp * 8;

    float4 acc[8];
    #pragma unroll
    for (int r = 0; r < 8; r++) acc[r] = make_float4(0.f, 0.f, 0.f, 0.f);

    for (int kk = 0; kk < 2; kk++) {
        {
            int r = tid >> 2;
            int cbase = (tid & 3) * 16;
            int grow = blockRow + r;
            #pragma unroll
            for (int j = 0; j < 4; j++) {
                float4 v = make_float4(0.f, 0.f, 0.f, 0.f);
                if (grow < N_NODES)
                    v = *(const float4*)&X[grow * DIM + kk * 64 + cbase + j * 4];
                *(float4*)&xs[r][cbase + j * 4] = v;
            }
            int wr = tid >> 2;
            int wc = (tid & 3) * 32;
            #pragma unroll
            for (int j = 0; j < 8; j++) {
                *(float4*)&ws[wr][wc + j * 4] =
                    *(const float4*)&W[(kk * 64 + wr) * DIM + wc + j * 4];
            }
        }
        __syncthreads();
        #pragma unroll 4
        for (int k = 0; k < 64; k++) {
            float4 w4 = *(float4*)&ws[k][lane * 4];
            #pragma unroll
            for (int r = 0; r < 8; r++) {
                float xv = xs[rbase + r][k];
                acc[r].x = fmaf(xv, w4.x, acc[r].x);
                acc[r].y = fmaf(xv, w4.y, acc[r].y);
                acc[r].z = fmaf(xv, w4.z, acc[r].z);
                acc[r].w = fmaf(xv, w4.w, acc[r].w);
            }
        }
        __syncthreads();
    }
    #pragma unroll
    for (int r = 0; r < 8; r++) {
        int grow = blockRow + rbase + r;
        if (grow < N_NODES)
            *(float4*)&g_t[grow * DIM + lane * 4] = acc[r];
    }
}

// ---------------- SpMM: out = relu(Anorm @ T + b) [+ dropout] ---------------
__global__ void k_spmm(const float* __restrict__ bias,
                       float* __restrict__ out_ext, int mode /*0:->g_h, 1:->out+dropout*/) {
    int warp = threadIdx.x >> 5;
    int lane = threadIdx.x & 31;
    int node = blockIdx.x * 8 + warp;
    if (node >= N_NODES) return;
    int c4 = lane * 4;

    float di = g_dinv[node];
    float wself = 2.0f * di * di;
    float4 v = *(const float4*)&g_t[node * DIM + c4];
    float4 acc;
    acc.x = wself * v.x; acc.y = wself * v.y;
    acc.z = wself * v.z; acc.w = wself * v.w;

    int s = g_off[node], e = g_off[node + 1];
    int i = s;
    for (; i + 1 < e; i += 2) {
        int r0 = g_src[i], r1 = g_src[i + 1];
        float w0 = g_nrm[i], w1 = g_nrm[i + 1];
        float4 v0 = *(const float4*)&g_t[r0 * DIM + c4];
        float4 v1 = *(const float4*)&g_t[r1 * DIM + c4];
        acc.x = fmaf(w0, v0.x, fmaf(w1, v1.x, acc.x));
        acc.y = fmaf(w0, v0.y, fmaf(w1, v1.y, acc.y));
        acc.z = fmaf(w0, v0.z, fmaf(w1, v1.z, acc.z));
        acc.w = fmaf(w0, v0.w, fmaf(w1, v1.w, acc.w));
    }
    if (i < e) {
        int r0 = g_src[i];
        float w0 = g_nrm[i];
        float4 v0 = *(const float4*)&g_t[r0 * DIM + c4];
        acc.x = fmaf(w0, v0.x, acc.x);
        acc.y = fmaf(w0, v0.y, acc.y);
        acc.z = fmaf(w0, v0.z, acc.z);
        acc.w = fmaf(w0, v0.w, acc.w);
    }

    float4 b4 = *(const float4*)&bias[c4];
    acc.x = fmaxf(acc.x + b4.x, 0.0f);
    acc.y = fmaxf(acc.y + b4.y, 0.0f);
    acc.z = fmaxf(acc.z + b4.z, 0.0f);
    acc.w = fmaxf(acc.w + b4.w, 0.0f);

    if (mode == 0) {
        *(float4*)&g_h[node * DIM + c4] = acc;
    } else {
        uchar4 k4 = *(const uchar4*)&g_keep[node * DIM + c4];
        acc.x = k4.x ? acc.x * 2.0f : 0.0f;
        acc.y = k4.y ? acc.y * 2.0f : 0.0f;
        acc.z = k4.z ? acc.z * 2.0f : 0.0f;
        acc.w = k4.w ? acc.w * 2.0f : 0.0f;
        *(float4*)&out_ext[node * DIM + c4] = acc;
    }
}

// ---------------- launch ----------------------------------------------------
extern "C" void kernel_launch(void* const* d_in, const int* in_sizes, int n_in,
                              void* d_out, int out_size) {
    const float* x  = (const float*)d_in[0];
    const void*  ei = d_in[1];
    const float* ew = (const float*)d_in[2];
    const float* W1 = (const float*)d_in[3];
    const float* b1 = (const float*)d_in[4];
    const float* W2 = (const float*)d_in[5];
    const float* b2 = (const float*)d_in[6];
    float* out = (float*)d_out;
    int E = in_sizes[2];           // edge_weight count = N_EDGES
    int n_idx = in_sizes[1];       // edge_index element count (2E)

    k_detect<<<1, 256>>>((const int*)ei, n_idx);
    k_init<<<(N_NODES + 255) / 256, 256>>>();
    k_deg<<<(E + 255) / 256, 256>>>(ei, ew, E);
    k_dinv<<<(N_NODES + 255) / 256, 256>>>();
    k_scan<<<1, 1024>>>();
    k_fill<<<(E + 255) / 256, 256>>>(ei, ew, E);
    k_mask<<<(MASK_N + 255) / 256, 256>>>();

    int gemmBlocks = (N_NODES + 63) / 64;
    int spmmBlocks = (N_NODES + 7) / 8;

    k_gemm<<<gemmBlocks, 256>>>(x, W1, 0);        // T = X @ W1
    k_spmm<<<spmmBlocks, 256>>>(b1, out, 0);      // g_h = relu(A T + b1)
    k_gemm<<<gemmBlocks, 256>>>(nullptr, W2, 1);  // T = g_h @ W2
    k_spmm<<<spmmBlocks, 256>>>(b2, out, 1);      // out = dropout(relu(A T + b2))
}

// round 7
// speedup vs baseline: 1.0059x; 1.0059x over previous
#include <cuda_runtime.h>
#include <cstdint>

#define N_NODES   50000
#define N_EDGES   800000
#define DIM       128

#define GEMM_BLOCKS  ((N_NODES + 63) / 64)      // 782
#define INIT_BLOCKS  ((N_NODES + 255) / 256)    // 196
#define SPMM_BLOCKS  ((N_NODES + 7) / 8)

// ---------------- scratch (static device globals; no allocations) ----------
__device__ float g_deg[N_NODES];
__device__ float g_dinv[N_NODES];
__device__ int   g_cnt[N_NODES];
__device__ int   g_off[N_NODES + 1];
__device__ int   g_cur[N_NODES];
__device__ int   g_src[N_EDGES];
__device__ float g_nrm[N_EDGES];
__device__ float g_t[N_NODES * DIM];   // GEMM output (per layer)
__device__ float g_h[N_NODES * DIM];   // layer-1 activation
__device__ int   g_is64;               // edge_index buffer dtype flag

__device__ __forceinline__ int load_idx(const void* ei, int pos) {
    if (g_is64) return (int)((const long long*)ei)[pos];
    return ((const int*)ei)[pos];
}

// ---------------- GEMM body: T = X @ W (shared by both launches) ------------
__device__ __forceinline__ void gemm_body(const float* __restrict__ X,
                                          const float* __restrict__ W,
                                          int blockRow,
                                          float (*xs)[64], float (*ws)[128]) {
    int tid = threadIdx.x;
    int warp = tid >> 5, lane = tid & 31;
    int rbase = warp * 8;

    float4 acc[8];
    #pragma unroll
    for (int r = 0; r < 8; r++) acc[r] = make_float4(0.f, 0.f, 0.f, 0.f);

    for (int kk = 0; kk < 2; kk++) {
        {
            int r = tid >> 2;
            int cbase = (tid & 3) * 16;
            int grow = blockRow + r;
            #pragma unroll
            for (int j = 0; j < 4; j++) {
                float4 v = make_float4(0.f, 0.f, 0.f, 0.f);
                if (grow < N_NODES)
                    v = *(const float4*)&X[grow * DIM + kk * 64 + cbase + j * 4];
                *(float4*)&xs[r][cbase + j * 4] = v;
            }
            int wr = tid >> 2;
            int wc = (tid & 3) * 32;
            #pragma unroll
            for (int j = 0; j < 8; j++) {
                *(float4*)&ws[wr][wc + j * 4] =
                    *(const float4*)&W[(kk * 64 + wr) * DIM + wc + j * 4];
            }
        }
        __syncthreads();
        #pragma unroll 4
        for (int k = 0; k < 64; k++) {
            float4 w4 = *(float4*)&ws[k][lane * 4];
            #pragma unroll
            for (int r = 0; r < 8; r++) {
                float xv = xs[rbase + r][k];
                acc[r].x = fmaf(xv, w4.x, acc[r].x);
                acc[r].y = fmaf(xv, w4.y, acc[r].y);
                acc[r].z = fmaf(xv, w4.z, acc[r].z);
                acc[r].w = fmaf(xv, w4.w, acc[r].w);
            }
        }
        __syncthreads();
    }
    #pragma unroll
    for (int r = 0; r < 8; r++) {
        int grow = blockRow + rbase + r;
        if (grow < N_NODES)
            *(float4*)&g_t[grow * DIM + lane * 4] = acc[r];
    }
}

// ---------------- launch 1: GEMM1 + init + dtype-detect (independent) -------
__global__ void k_fused1(const float* __restrict__ x,
                         const float* __restrict__ W1,
                         const int* __restrict__ ei32, int n32) {
    __shared__ float xs[64][64];     // 16KB
    __shared__ float ws[64][128];    // 32KB  (total = 48KB exactly; add nothing)
    int b = blockIdx.x;
    if (b < GEMM_BLOCKS) {
        gemm_body(x, W1, b * 64, xs, ws);
    } else if (b < GEMM_BLOCKS + INIT_BLOCKS) {
        int i = (b - GEMM_BLOCKS) * 256 + threadIdx.x;
        if (i < N_NODES) { g_deg[i] = 2.0f; g_cnt[i] = 0; }  // self-loop w=2
    } else {
        // dtype detect: int64 => all odd int32 words zero (values < 50000).
        // __syncthreads_or does the block reduce without shared memory.
        int nz = 0;
        for (int i = threadIdx.x; i < 4096; i += blockDim.x) {
            int p = 2 * i + 1;
            if (p < n32 && ei32[p] != 0) nz = 1;
        }
        int any = __syncthreads_or(nz);
        if (threadIdx.x == 0) g_is64 = any ? 0 : 1;
    }
}

// ---------------- launch 2: degree + per-col counts --------------------------
__global__ void k_deg(const void* __restrict__ ei,
                      const float* __restrict__ ew, int E) {
    int e = blockIdx.x * blockDim.x + threadIdx.x;
    if (e >= E) return;
    int c = load_idx(ei, E + e);
    if ((unsigned)c < N_NODES) {
        atomicAdd(&g_deg[c], ew[e]);
        atomicAdd(&g_cnt[c], 1);
    }
}

// ---------------- launch 3: dinv + exclusive scan (single block) -------------
__global__ void k_scan() {
    __shared__ int sh_warp[32];
    __shared__ int sh_carry;
    int tid = threadIdx.x, lane = tid & 31, wid = tid >> 5;

    for (int i = tid; i < N_NODES; i += 1024) {
        float d = g_deg[i];
        g_dinv[i] = (d > 0.0f) ? rsqrtf(d) : 0.0f;
    }

    if (tid == 0) sh_carry = 0;
    __syncthreads();
    for (int base = 0; base < N_NODES; base += 1024) {
        int i = base + tid;
        int v = (i < N_NODES) ? g_cnt[i] : 0;
        int x = v;
        #pragma unroll
        for (int o = 1; o < 32; o <<= 1) {
            int y = __shfl_up_sync(0xFFFFFFFFu, x, o);
            if (lane >= o) x += y;
        }
        if (lane == 31) sh_warp[wid] = x;
        __syncthreads();
        if (wid == 0) {
            int s = sh_warp[lane];
            #pragma unroll
            for (int o = 1; o < 32; o <<= 1) {
                int y = __shfl_up_sync(0xFFFFFFFFu, s, o);
                if (lane >= o) s += y;
            }
            sh_warp[lane] = s;
        }
        __syncthreads();
        int warppref = (wid == 0) ? 0 : sh_warp[wid - 1];
        int incl = x + warppref;
        int excl = sh_carry + incl - v;
        if (i < N_NODES) { g_off[i] = excl; g_cur[i] = excl; }
        __syncthreads();
        if (tid == 1023) sh_carry += sh_warp[31];
        __syncthreads();
    }
    if (threadIdx.x == 0) g_off[N_NODES] = sh_carry;
}

// ---------------- launch 4: CSR fill + edge norms ----------------------------
__global__ void k_fill(const void* __restrict__ ei,
                       const float* __restrict__ ew, int E) {
    int e = blockIdx.x * blockDim.x + threadIdx.x;
    if (e >= E) return;
    int r = load_idx(ei, e);
    int c = load_idx(ei, E + e);
    if ((unsigned)r >= N_NODES || (unsigned)c >= N_NODES) return;
    int p = atomicAdd(&g_cur[c], 1);
    if ((unsigned)p < N_EDGES) {
        g_src[p] = r;
        g_nrm[p] = g_dinv[r] * ew[e] * g_dinv[c];
    }
}

// ---------------- JAX threefry (partitionable, verified round 4) -------------
__device__ __forceinline__ unsigned rotl32(unsigned v, int d) {
    return (v << d) | (v >> (32 - d));
}
__device__ __forceinline__ unsigned tf_bits(unsigned c1) {
    const unsigned k0 = 0u, k1 = 42u;
    const unsigned k2 = k0 ^ k1 ^ 0x1BD11BDAu;
    unsigned x0 = 0u + k0, x1 = c1 + k1;
#define TF_R(rot) { x0 += x1; x1 = rotl32(x1, rot); x1 ^= x0; }
    TF_R(13) TF_R(15) TF_R(26) TF_R(6)   x0 += k1; x1 += k2 + 1u;
    TF_R(17) TF_R(29) TF_R(16) TF_R(24)  x0 += k2; x1 += k0 + 2u;
    TF_R(13) TF_R(15) TF_R(26) TF_R(6)   x0 += k0; x1 += k1 + 3u;
    TF_R(17) TF_R(29) TF_R(16) TF_R(24)  x0 += k1; x1 += k2 + 4u;
    TF_R(13) TF_R(15) TF_R(26) TF_R(6)   x0 += k2; x1 += k0 + 5u;
#undef TF_R
    return x0 ^ x1;   // partitionable 32-bit fold; keep <=> bit31 == 0
}

// ---------------- SpMM: out = relu(A T + b) [+ inline dropout] ---------------
template <int MODE>   // 0: -> g_h, 1: -> out with inline threefry dropout
__global__ void k_spmm(const float* __restrict__ bias,
                       float* __restrict__ out_ext) {
    int warp = threadIdx.x >> 5;
    int lane = threadIdx.x & 31;
    int node = blockIdx.x * 8 + warp;
    if (node >= N_NODES) return;
    int c4 = lane * 4;

    float di = g_dinv[node];
    float wself = 2.0f * di * di;
    float4 v = *(const float4*)&g_t[node * DIM + c4];
    float4 a0, a1, a2, a3;
    a0.x = wself * v.x; a0.y = wself * v.y; a0.z = wself * v.z; a0.w = wself * v.w;
    a1 = make_float4(0.f, 0.f, 0.f, 0.f);
    a2 = make_float4(0.f, 0.f, 0.f, 0.f);
    a3 = make_float4(0.f, 0.f, 0.f, 0.f);

    int s = g_off[node], e = g_off[node + 1];
    int i = s;
    for (; i + 3 < e; i += 4) {
        int   r0 = g_src[i],     r1 = g_src[i + 1];
        int   r2 = g_src[i + 2], r3 = g_src[i + 3];
        float w0 = g_nrm[i],     w1 = g_nrm[i + 1];
        float w2 = g_nrm[i + 2], w3 = g_nrm[i + 3];
        float4 v0 = *(const float4*)&g_t[r0 * DIM + c4];
        float4 v1 = *(const float4*)&g_t[r1 * DIM + c4];
        float4 v2 = *(const float4*)&g_t[r2 * DIM + c4];
        float4 v3 = *(const float4*)&g_t[r3 * DIM + c4];
        a0.x = fmaf(w0, v0.x, a0.x); a0.y = fmaf(w0, v0.y, a0.y);
        a0.z = fmaf(w0, v0.z, a0.z); a0.w = fmaf(w0, v0.w, a0.w);
        a1.x = fmaf(w1, v1.x, a1.x); a1.y = fmaf(w1, v1.y, a1.y);
        a1.z = fmaf(w1, v1.z, a1.z); a1.w = fmaf(w1, v1.w, a1.w);
        a2.x = fmaf(w2, v2.x, a2.x); a2.y = fmaf(w2, v2.y, a2.y);
        a2.z = fmaf(w2, v2.z, a2.z); a2.w = fmaf(w2, v2.w, a2.w);
        a3.x = fmaf(w3, v3.x, a3.x); a3.y = fmaf(w3, v3.y, a3.y);
        a3.z = fmaf(w3, v3.z, a3.z); a3.w = fmaf(w3, v3.w, a3.w);
    }
    for (; i < e; i++) {
        int r0 = g_src[i];
        float w0 = g_nrm[i];
        float4 v0 = *(const float4*)&g_t[r0 * DIM + c4];
        a0.x = fmaf(w0, v0.x, a0.x); a0.y = fmaf(w0, v0.y, a0.y);
        a0.z = fmaf(w0, v0.z, a0.z); a0.w = fmaf(w0, v0.w, a0.w);
    }

    float4 acc;
    acc.x = (a0.x + a1.x) + (a2.x + a3.x);
    acc.y = (a0.y + a1.y) + (a2.y + a3.y);
    acc.z = (a0.z + a1.z) + (a2.z + a3.z);
    acc.w = (a0.w + a1.w) + (a2.w + a3.w);

    float4 b4 = *(const float4*)&bias[c4];
    acc.x = fmaxf(acc.x + b4.x, 0.0f);
    acc.y = fmaxf(acc.y + b4.y, 0.0f);
    acc.z = fmaxf(acc.z + b4.z, 0.0f);
    acc.w = fmaxf(acc.w + b4.w, 0.0f);

    if (MODE == 0) {
        *(float4*)&g_h[node * DIM + c4] = acc;
    } else {
        unsigned base = (unsigned)(node * DIM + c4);
        acc.x = (tf_bits(base + 0u) >> 31) ? 0.0f : acc.x * 2.0f;
        acc.y = (tf_bits(base + 1u) >> 31) ? 0.0f : acc.y * 2.0f;
        acc.z = (tf_bits(base + 2u) >> 31) ? 0.0f : acc.z * 2.0f;
        acc.w = (tf_bits(base + 3u) >> 31) ? 0.0f : acc.w * 2.0f;
        *(float4*)&out_ext[node * DIM + c4] = acc;
    }
}

// ---------------- launch 6: GEMM2 (reads g_h) --------------------------------
__global__ void k_gemm2(const float* __restrict__ W2) {
    __shared__ float xs[64][64];
    __shared__ float ws[64][128];
    gemm_body(g_h, W2, blockIdx.x * 64, xs, ws);
}

// ---------------- launch ----------------------------------------------------
extern "C" void kernel_launch(void* const* d_in, const int* in_sizes, int n_in,
                              void* d_out, int out_size) {
    const float* x  = (const float*)d_in[0];
    const void*  ei = d_in[1];
    const float* ew = (const float*)d_in[2];
    const float* W1 = (const float*)d_in[3];
    const float* b1 = (const float*)d_in[4];
    const float* W2 = (const float*)d_in[5];
    const float* b2 = (const float*)d_in[6];
    float* out = (float*)d_out;
    int E = in_sizes[2];           // N_EDGES
    int n_idx = in_sizes[1];       // edge_index element count

    k_fused1<<<GEMM_BLOCKS + INIT_BLOCKS + 1, 256>>>(x, W1, (const int*)ei, n_idx);
    k_deg<<<(E + 255) / 256, 256>>>(ei, ew, E);
    k_scan<<<1, 1024>>>();
    k_fill<<<(E + 255) / 256, 256>>>(ei, ew, E);
    k_spmm<0><<<SPMM_BLOCKS, 256>>>(b1, out);   // g_h = relu(A T + b1)
    k_gemm2<<<GEMM_BLOCKS, 256>>>(W2);          // T = g_h @ W2
    k_spmm<1><<<SPMM_BLOCKS, 256>>>(b2, out);   // out = dropout(relu(A T + b2))
}